// round 13
// baseline (speedup 1.0000x reference)
#include <cuda_runtime.h>

#define DIN   400
#define DOUT  100
#define NQ    10
#define NT    128
#define XPAD  12             // padded X row, 16B-aligned rows
#define APAD  11             // odd stride -> conflict-free QR column access
#define NP    50             // o-pairs total
#define NLP   25             // o-pairs per warp (lanes 0..24 active)
#define KH    200            // k-half per warp pair

// W packed by o-pair: g_Wp2[k*NP + p] = {W[2p][k], W[2p+1][k]}
__device__ float2 g_Wp2[DIN * NP];

__global__ void pack_w_kernel(const float* __restrict__ W) {
    int idx = blockIdx.x * blockDim.x + threadIdx.x;
    if (idx < DIN * NP) {
        int k = idx / NP;
        int p = idx - k * NP;
        float2 v;
        v.x = W[(2 * p + 0) * DIN + k];
        v.y = W[(2 * p + 1) * DIN + k];
        g_Wp2[idx] = v;
    }
}

__device__ __forceinline__ float xor_sum(float x) {
    x += __shfl_xor_sync(0xffffffffu, x, 16);
    x += __shfl_xor_sync(0xffffffffu, x, 8);
    x += __shfl_xor_sync(0xffffffffu, x, 4);
    x += __shfl_xor_sync(0xffffffffu, x, 2);
    x += __shfl_xor_sync(0xffffffffu, x, 1);
    return x;
}

// ---- packed f32x2 helpers (FFMA2 via PTX; ptxas never emits from C++) ----
__device__ __forceinline__ unsigned long long pack2(float x) {
    unsigned long long r;
    asm("mov.b64 %0, {%1, %1};" : "=l"(r) : "f"(x));
    return r;
}
__device__ __forceinline__ void fma2(unsigned long long& d,
                                     unsigned long long a,
                                     unsigned long long b) {
    asm("fma.rn.f32x2 %0, %1, %2, %0;" : "+l"(d) : "l"(a), "l"(b));
}
__device__ __forceinline__ void unpack2(unsigned long long v, float& lo, float& hi) {
    asm("mov.b64 {%0, %1}, %2;" : "=f"(lo), "=f"(hi) : "l"(v));
}

__global__ __launch_bounds__(NT, 8) void frmap_qr_kernel(
    const float* __restrict__ X,   // (B, DIN, NQ)
    float* __restrict__ out)       // (B, DOUT, NQ)
{
    __shared__ __align__(16) float Xs[DIN * XPAD];   // 19.2 KB; reused: partials, then Qs
    __shared__ float As[DOUT * APAD];                // 4.4 KB
    __shared__ float Vs[NQ * DOUT];                  // 4.0 KB
    __shared__ float tau_sh[NQ];

    const int tid  = threadIdx.x;
    const int b    = blockIdx.x;
    const int lane = tid & 31;
    const int wrp  = tid >> 5;
    const int qw   = b & 3;        // rotate QR warp across SMSPs per block

    // ---- load X[b] into padded smem ----
    {
        const float2* Xb2 = (const float2*)(X + (long long)b * (DIN * NQ));
        for (int m = tid; m < (DIN * NQ) / 2; m += NT) {
            float2 v = Xb2[m];
            int f = 2 * m;
            int i = f / 10;
            int q = f - i * 10;
            Xs[i * XPAD + q]     = v.x;
            Xs[i * XPAD + q + 1] = v.y;
        }
    }
    __syncthreads();

    // ---- GEMM, 2x2 split: warp w = (kh = w>>1, oh = w&1).
    //      lane l<25 owns o-pair 2*(25*oh+l), all 10 q (10 f32x2 accumulators) ----
    unsigned long long acc[2][5];
    #pragma unroll
    for (int j = 0; j < 2; j++)
        #pragma unroll
        for (int p = 0; p < 5; p++) acc[j][p] = 0ull;

    const int oh = wrp & 1;
    const int kh = wrp >> 1;
    const int k0 = kh * KH;

    if (lane < NLP) {
        const float2* Wp = g_Wp2 + (long long)k0 * NP + NLP * oh + lane;
        // depth-4 rolling prefetch of W (MLP 4)
        float2 wb[4];
        wb[0] = Wp[0 * NP];
        wb[1] = Wp[1 * NP];
        wb[2] = Wp[2 * NP];
        wb[3] = Wp[3 * NP];
        const float2* Wpre = Wp + 4 * NP;

        #pragma unroll 4
        for (int kk = 0; kk < KH - 4; kk++) {
            float2 w = wb[kk & 3];
            wb[kk & 3] = *Wpre;            // prefetch k0+kk+4
            Wpre += NP;
            const float* xr = &Xs[(k0 + kk) * XPAD];   // broadcast row
            ulonglong2 xab = *(const ulonglong2*)(xr);       // q0..3
            ulonglong2 xcd = *(const ulonglong2*)(xr + 4);   // q4..7
            unsigned long long xe = *(const unsigned long long*)(xr + 8); // q8,9
            unsigned long long w0 = pack2(w.x);
            unsigned long long w1 = pack2(w.y);
            fma2(acc[0][0], w0, xab.x); fma2(acc[0][1], w0, xab.y);
            fma2(acc[0][2], w0, xcd.x); fma2(acc[0][3], w0, xcd.y);
            fma2(acc[0][4], w0, xe);
            fma2(acc[1][0], w1, xab.x); fma2(acc[1][1], w1, xab.y);
            fma2(acc[1][2], w1, xcd.x); fma2(acc[1][3], w1, xcd.y);
            fma2(acc[1][4], w1, xe);
        }
        // drain tail (4 iterations, no prefetch)
        #pragma unroll
        for (int kk = KH - 4; kk < KH; kk++) {
            float2 w = wb[kk & 3];
            const float* xr = &Xs[(k0 + kk) * XPAD];
            ulonglong2 xab = *(const ulonglong2*)(xr);
            ulonglong2 xcd = *(const ulonglong2*)(xr + 4);
            unsigned long long xe = *(const unsigned long long*)(xr + 8);
            unsigned long long w0 = pack2(w.x);
            unsigned long long w1 = pack2(w.y);
            fma2(acc[0][0], w0, xab.x); fma2(acc[0][1], w0, xab.y);
            fma2(acc[0][2], w0, xcd.x); fma2(acc[0][3], w0, xcd.y);
            fma2(acc[0][4], w0, xe);
            fma2(acc[1][0], w1, xab.x); fma2(acc[1][1], w1, xab.y);
            fma2(acc[1][2], w1, xcd.x); fma2(acc[1][3], w1, xcd.y);
            fma2(acc[1][4], w1, xe);
        }
    }
    __syncthreads();      // all warps done reading Xs

    // ---- stash per-warp partials into (dead) Xs region ----
    // layout: part[wrp*250 + l*10 + j*5 + p]  (u64 each), 4*250*8B = 8 KB
    {
        unsigned long long* part = (unsigned long long*)Xs;
        if (lane < NLP) {
            int base = wrp * 250 + lane * 10;
            #pragma unroll
            for (int j = 0; j < 2; j++)
                #pragma unroll
                for (int p = 0; p < 5; p++)
                    part[base + j * 5 + p] = acc[j][p];
        }
    }
    __syncthreads();

    // ---- reduce 2 k-halves -> As ----
    if (tid < DOUT) {
        const unsigned long long* part = (const unsigned long long*)Xs;
        int o  = tid;
        int op = o >> 1, j = o & 1;
        int ohh = op / NLP;            // which o-half
        int l   = op - ohh * NLP;
        int w0i = (0 << 1) | ohh;      // warp (kh=0, oh)
        int w1i = (1 << 1) | ohh;      // warp (kh=1, oh)
        #pragma unroll
        for (int p = 0; p < 5; p++) {
            float ax, ay, bx, by;
            unpack2(part[w0i * 250 + l * 10 + j * 5 + p], ax, ay);
            unpack2(part[w1i * 250 + l * 10 + j * 5 + p], bx, by);
            As[o * APAD + 2 * p]     = ax + bx;
            As[o * APAD + 2 * p + 1] = ay + by;
        }
    }
    __syncthreads();

    // ---- QR by one warp (rotated per block): barrier-free shfl_xor reductions ----
    if (wrp == qw) {
        // Householder, LAPACK slarfg convention
        #pragma unroll 1
        for (int j = 0; j < NQ; j++) {
            float aj[4];
            #pragma unroll
            for (int r = 0; r < 4; r++) {
                int row = lane + 32 * r;
                aj[r] = (row < DOUT) ? As[row * APAD + j] : 0.f;
            }
            float alpha = __shfl_sync(0xffffffffu, aj[0], j);   // row j: lane j, r=0
            float s = 0.f;
            #pragma unroll
            for (int r = 0; r < 4; r++) {
                int row = lane + 32 * r;
                if (row < DOUT && row > j) s += aj[r] * aj[r];
            }
            s = xor_sum(s);

            float tau, inv_amb;
            if (s <= 0.f) {
                tau = 0.f; inv_amb = 0.f;
            } else {
                float nrm  = sqrtf(alpha * alpha + s);
                float beta = (alpha >= 0.f) ? -nrm : nrm;   // beta = -sign(alpha)*||x||
                tau     = (beta - alpha) / beta;
                inv_amb = 1.f / (alpha - beta);
            }
            if (lane == 0) tau_sh[j] = tau;

            float v[4];
            #pragma unroll
            for (int r = 0; r < 4; r++) {
                int row = lane + 32 * r;
                float vv = 0.f;
                if (row == j)                    vv = 1.f;
                else if (row > j && row < DOUT)  vv = aj[r] * inv_amb;
                v[r] = vv;
                if (row < DOUT) Vs[j * DOUT + row] = vv;
            }

            // trailing update: A[:,k] -= v * tau * (v . A[:,k]) for k > j
            #pragma unroll
            for (int k = 0; k < NQ; k++) {
                if (k > j) {                       // uniform branch across warp
                    float d = 0.f;
                    #pragma unroll
                    for (int r = 0; r < 4; r++) {
                        int row = lane + 32 * r;
                        if (row < DOUT) d += v[r] * As[row * APAD + k];
                    }
                    d = xor_sum(d);
                    float c = tau * d;
                    #pragma unroll
                    for (int r = 0; r < 4; r++) {
                        int row = lane + 32 * r;
                        if (row < DOUT) As[row * APAD + k] -= v[r] * c;
                    }
                }
            }
        }

        // orgqr: Q = H_0..H_9 * I(:,0:10), backward accumulation, in registers
        float q[4][NQ];
        #pragma unroll
        for (int r = 0; r < 4; r++) {
            int row = lane + 32 * r;
            #pragma unroll
            for (int k = 0; k < NQ; k++) q[r][k] = (row == k) ? 1.f : 0.f;
        }

        #pragma unroll 1
        for (int j = NQ - 1; j >= 0; j--) {
            float v[4];
            #pragma unroll
            for (int r = 0; r < 4; r++) {
                int row = lane + 32 * r;
                v[r] = (row < DOUT) ? Vs[j * DOUT + row] : 0.f;
            }
            float tj = tau_sh[j];
            #pragma unroll
            for (int k = 0; k < NQ; k++) {
                if (k >= j) {                      // columns k<j are still e_k
                    float d = 0.f;
                    #pragma unroll
                    for (int r = 0; r < 4; r++) d += v[r] * q[r][k];
                    d = xor_sum(d);
                    float c = tj * d;
                    #pragma unroll
                    for (int r = 0; r < 4; r++) q[r][k] -= v[r] * c;
                }
            }
        }

        // stage Q into smem (reuse Xs region, partials dead) for a vector write
        float* Qs = Xs;
        #pragma unroll
        for (int r = 0; r < 4; r++) {
            int row = lane + 32 * r;
            if (row < DOUT) {
                #pragma unroll
                for (int k = 0; k < NQ; k++) Qs[row * NQ + k] = q[r][k];
            }
        }
    }
    __syncthreads();

    // ---- coalesced float4 write-out (1000 floats = 250 float4) ----
    {
        const float4* Qs4 = (const float4*)Xs;
        float4* out4 = (float4*)(out + (long long)b * (DOUT * NQ));
        for (int m = tid; m < (DOUT * NQ) / 4; m += NT) out4[m] = Qs4[m];
    }
}

extern "C" void kernel_launch(void* const* d_in, const int* in_sizes, int n_in,
                              void* d_out, int out_size)
{
    const float* X = (const float*)d_in[0];
    const float* W = (const float*)d_in[1];
    if (n_in >= 2 && in_sizes[0] == DOUT * DIN && in_sizes[1] != DOUT * DIN) {
        const float* t = X; X = W; W = t;
    }
    pack_w_kernel<<<(DIN * NP + 255) / 256, 256>>>(W);
    int batches = out_size / (DOUT * NQ);
    frmap_qr_kernel<<<batches, NT>>>(X, (float*)d_out);
}

// round 14
// speedup vs baseline: 1.1302x; 1.1302x over previous
#include <cuda_runtime.h>

#define DIN   400
#define DOUT  100
#define NQ    10
#define NT    128
#define APAD  11             // odd stride -> conflict-free QR column access
#define NP    50             // o-pairs total
#define NLP   25             // o-pairs per warp (lanes 0..24 active)
#define NKP   200            // k-pairs total
#define KPH   100            // k-pairs per k-half

// W packed per (k-pair, o-pair): {W[2p][2t], W[2p+1][2t], W[2p][2t+1], W[2p+1][2t+1]}
__device__ float4 g_W4[NKP * NP];

__global__ void pack_w_kernel(const float* __restrict__ W) {
    int idx = blockIdx.x * blockDim.x + threadIdx.x;
    if (idx < NKP * NP) {
        int t = idx / NP;
        int p = idx - t * NP;
        float4 v;
        v.x = W[(2 * p + 0) * DIN + 2 * t + 0];
        v.y = W[(2 * p + 1) * DIN + 2 * t + 0];
        v.z = W[(2 * p + 0) * DIN + 2 * t + 1];
        v.w = W[(2 * p + 1) * DIN + 2 * t + 1];
        g_W4[idx] = v;
    }
}

__device__ __forceinline__ float xor_sum(float x) {
    x += __shfl_xor_sync(0xffffffffu, x, 16);
    x += __shfl_xor_sync(0xffffffffu, x, 8);
    x += __shfl_xor_sync(0xffffffffu, x, 4);
    x += __shfl_xor_sync(0xffffffffu, x, 2);
    x += __shfl_xor_sync(0xffffffffu, x, 1);
    return x;
}

// ---- packed f32x2 helpers (FFMA2 via PTX; ptxas never emits from C++) ----
__device__ __forceinline__ unsigned long long pack2(float x) {
    unsigned long long r;
    asm("mov.b64 %0, {%1, %1};" : "=l"(r) : "f"(x));
    return r;
}
__device__ __forceinline__ void fma2(unsigned long long& d,
                                     unsigned long long a,
                                     unsigned long long b) {
    asm("fma.rn.f32x2 %0, %1, %2, %0;" : "+l"(d) : "l"(a), "l"(b));
}
__device__ __forceinline__ void unpack2(unsigned long long v, float& lo, float& hi) {
    asm("mov.b64 {%0, %1}, %2;" : "=f"(lo), "=f"(hi) : "l"(v));
}

__global__ __launch_bounds__(NT, 9) void frmap_qr_kernel(
    const float* __restrict__ X,   // (B, DIN, NQ)
    float* __restrict__ out)       // (B, DOUT, NQ)
{
    __shared__ __align__(16) float Xs[DIN * NQ];     // 16 KB unpadded; reused: partials, Qs
    __shared__ float As[DOUT * APAD];                // 4.4 KB
    __shared__ float Vs[NQ * DOUT];                  // 4.0 KB
    __shared__ float tau_sh[NQ];

    const int tid  = threadIdx.x;
    const int b    = blockIdx.x;
    const int lane = tid & 31;
    const int wrp  = tid >> 5;
    const int qw   = b & 3;        // rotate QR warp across SMSPs per block

    // ---- load X[b]: straight vectorized copy (4000 floats = 1000 float4) ----
    {
        const float4* Xb4 = (const float4*)(X + (long long)b * (DIN * NQ));
        float4* Xs4 = (float4*)Xs;
        #pragma unroll
        for (int m = 0; m < 8; m++) {
            int i = tid + m * NT;
            if (m < 7 || i < 1000) Xs4[i] = Xb4[i];
        }
    }
    __syncthreads();

    // ---- GEMM, 2x2 split: warp w = (kh = w>>1, oh = w&1).
    //      lane l<25 owns o-pair 2*(25*oh+l), 10 f32x2 accumulators ----
    unsigned long long acc[2][5];
    #pragma unroll
    for (int j = 0; j < 2; j++)
        #pragma unroll
        for (int p = 0; p < 5; p++) acc[j][p] = 0ull;

    const int oh = wrp & 1;
    const int kh = wrp >> 1;
    const int t0 = kh * KPH;       // starting k-pair

    if (lane < NLP) {
        const float4* Wp = g_W4 + t0 * NP + NLP * oh + lane;
        float4 wb[2];
        wb[0] = Wp[0];
        wb[1] = Wp[NP];
        const float4* Wpre = Wp + 2 * NP;

        #pragma unroll 2
        for (int t = 0; t < KPH - 2; t++) {
            float4 w = wb[t & 1];
            wb[t & 1] = *Wpre;                 // prefetch t+2 (L2-resident)
            Wpre += NP;
            const float* xr = &Xs[(t0 + t) * 20];   // 20 floats = rows 2t, 2t+1; 16B aligned
            // even row (k = 2(t0+t))
            {
                ulonglong2 c0 = *(const ulonglong2*)(xr);        // q0q1,q2q3
                ulonglong2 c1 = *(const ulonglong2*)(xr + 4);    // q4q5,q6q7
                unsigned long long c2x = *(const unsigned long long*)(xr + 8); // q8q9
                unsigned long long w0 = pack2(w.x);
                unsigned long long w1 = pack2(w.y);
                fma2(acc[0][0], w0, c0.x); fma2(acc[0][1], w0, c0.y);
                fma2(acc[0][2], w0, c1.x); fma2(acc[0][3], w0, c1.y);
                fma2(acc[0][4], w0, c2x);
                fma2(acc[1][0], w1, c0.x); fma2(acc[1][1], w1, c0.y);
                fma2(acc[1][2], w1, c1.x); fma2(acc[1][3], w1, c1.y);
                fma2(acc[1][4], w1, c2x);
            }
            // odd row (k = 2(t0+t)+1)
            {
                unsigned long long d0 = *(const unsigned long long*)(xr + 10); // q0q1
                ulonglong2 c3 = *(const ulonglong2*)(xr + 12);   // q2q3,q4q5
                ulonglong2 c4 = *(const ulonglong2*)(xr + 16);   // q6q7,q8q9
                unsigned long long w2 = pack2(w.z);
                unsigned long long w3 = pack2(w.w);
                fma2(acc[0][0], w2, d0);
                fma2(acc[0][1], w2, c3.x); fma2(acc[0][2], w2, c3.y);
                fma2(acc[0][3], w2, c4.x); fma2(acc[0][4], w2, c4.y);
                fma2(acc[1][0], w3, d0);
                fma2(acc[1][1], w3, c3.x); fma2(acc[1][2], w3, c3.y);
                fma2(acc[1][3], w3, c4.x); fma2(acc[1][4], w3, c4.y);
            }
        }
        // drain tail (2 k-pairs, no prefetch)
        #pragma unroll
        for (int t = KPH - 2; t < KPH; t++) {
            float4 w = wb[t & 1];
            const float* xr = &Xs[(t0 + t) * 20];
            {
                ulonglong2 c0 = *(const ulonglong2*)(xr);
                ulonglong2 c1 = *(const ulonglong2*)(xr + 4);
                unsigned long long c2x = *(const unsigned long long*)(xr + 8);
                unsigned long long w0 = pack2(w.x);
                unsigned long long w1 = pack2(w.y);
                fma2(acc[0][0], w0, c0.x); fma2(acc[0][1], w0, c0.y);
                fma2(acc[0][2], w0, c1.x); fma2(acc[0][3], w0, c1.y);
                fma2(acc[0][4], w0, c2x);
                fma2(acc[1][0], w1, c0.x); fma2(acc[1][1], w1, c0.y);
                fma2(acc[1][2], w1, c1.x); fma2(acc[1][3], w1, c1.y);
                fma2(acc[1][4], w1, c2x);
            }
            {
                unsigned long long d0 = *(const unsigned long long*)(xr + 10);
                ulonglong2 c3 = *(const ulonglong2*)(xr + 12);
                ulonglong2 c4 = *(const ulonglong2*)(xr + 16);
                unsigned long long w2 = pack2(w.z);
                unsigned long long w3 = pack2(w.w);
                fma2(acc[0][0], w2, d0);
                fma2(acc[0][1], w2, c3.x); fma2(acc[0][2], w2, c3.y);
                fma2(acc[0][3], w2, c4.x); fma2(acc[0][4], w2, c4.y);
                fma2(acc[1][0], w3, d0);
                fma2(acc[1][1], w3, c3.x); fma2(acc[1][2], w3, c3.y);
                fma2(acc[1][3], w3, c4.x); fma2(acc[1][4], w3, c4.y);
            }
        }
    }
    __syncthreads();      // all warps done reading Xs

    // ---- stash per-warp partials into (dead) Xs region ----
    // layout: part[wrp*250 + l*10 + j*5 + p]  (u64 each) = 8 KB
    {
        unsigned long long* part = (unsigned long long*)Xs;
        if (lane < NLP) {
            int base = wrp * 250 + lane * 10;
            #pragma unroll
            for (int j = 0; j < 2; j++)
                #pragma unroll
                for (int p = 0; p < 5; p++)
                    part[base + j * 5 + p] = acc[j][p];
        }
    }
    __syncthreads();

    // ---- reduce 2 k-halves -> As ----
    if (tid < DOUT) {
        const unsigned long long* part = (const unsigned long long*)Xs;
        int o  = tid;
        int op = o >> 1, j = o & 1;
        int ohh = op / NLP;            // which o-half
        int l   = op - ohh * NLP;
        int w0i = (0 << 1) | ohh;      // warp (kh=0, oh)
        int w1i = (1 << 1) | ohh;      // warp (kh=1, oh)
        #pragma unroll
        for (int p = 0; p < 5; p++) {
            float ax, ay, bx, by;
            unpack2(part[w0i * 250 + l * 10 + j * 5 + p], ax, ay);
            unpack2(part[w1i * 250 + l * 10 + j * 5 + p], bx, by);
            As[o * APAD + 2 * p]     = ax + bx;
            As[o * APAD + 2 * p + 1] = ay + by;
        }
    }
    __syncthreads();

    // ---- QR by one warp (rotated per block): barrier-free shfl_xor reductions ----
    if (wrp == qw) {
        // Householder, LAPACK slarfg convention
        #pragma unroll 1
        for (int j = 0; j < NQ; j++) {
            float aj[4];
            #pragma unroll
            for (int r = 0; r < 4; r++) {
                int row = lane + 32 * r;
                aj[r] = (row < DOUT) ? As[row * APAD + j] : 0.f;
            }
            float alpha = __shfl_sync(0xffffffffu, aj[0], j);   // row j: lane j, r=0
            float s = 0.f;
            #pragma unroll
            for (int r = 0; r < 4; r++) {
                int row = lane + 32 * r;
                if (row < DOUT && row > j) s += aj[r] * aj[r];
            }
            s = xor_sum(s);

            float tau, inv_amb;
            if (s <= 0.f) {
                tau = 0.f; inv_amb = 0.f;
            } else {
                float nrm  = sqrtf(alpha * alpha + s);
                float beta = (alpha >= 0.f) ? -nrm : nrm;   // beta = -sign(alpha)*||x||
                tau     = (beta - alpha) / beta;
                inv_amb = 1.f / (alpha - beta);
            }
            if (lane == 0) tau_sh[j] = tau;

            float v[4];
            #pragma unroll
            for (int r = 0; r < 4; r++) {
                int row = lane + 32 * r;
                float vv = 0.f;
                if (row == j)                    vv = 1.f;
                else if (row > j && row < DOUT)  vv = aj[r] * inv_amb;
                v[r] = vv;
                if (row < DOUT) Vs[j * DOUT + row] = vv;
            }

            // trailing update: A[:,k] -= v * tau * (v . A[:,k]) for k > j
            #pragma unroll
            for (int k = 0; k < NQ; k++) {
                if (k > j) {                       // uniform branch across warp
                    float d = 0.f;
                    #pragma unroll
                    for (int r = 0; r < 4; r++) {
                        int row = lane + 32 * r;
                        if (row < DOUT) d += v[r] * As[row * APAD + k];
                    }
                    d = xor_sum(d);
                    float c = tau * d;
                    #pragma unroll
                    for (int r = 0; r < 4; r++) {
                        int row = lane + 32 * r;
                        if (row < DOUT) As[row * APAD + k] -= v[r] * c;
                    }
                }
            }
        }

        // orgqr: Q = H_0..H_9 * I(:,0:10), backward accumulation, in registers
        float q[4][NQ];
        #pragma unroll
        for (int r = 0; r < 4; r++) {
            int row = lane + 32 * r;
            #pragma unroll
            for (int k = 0; k < NQ; k++) q[r][k] = (row == k) ? 1.f : 0.f;
        }

        #pragma unroll 1
        for (int j = NQ - 1; j >= 0; j--) {
            float v[4];
            #pragma unroll
            for (int r = 0; r < 4; r++) {
                int row = lane + 32 * r;
                v[r] = (row < DOUT) ? Vs[j * DOUT + row] : 0.f;
            }
            float tj = tau_sh[j];
            #pragma unroll
            for (int k = 0; k < NQ; k++) {
                if (k >= j) {                      // columns k<j are still e_k
                    float d = 0.f;
                    #pragma unroll
                    for (int r = 0; r < 4; r++) d += v[r] * q[r][k];
                    d = xor_sum(d);
                    float c = tj * d;
                    #pragma unroll
                    for (int r = 0; r < 4; r++) q[r][k] -= v[r] * c;
                }
            }
        }

        // stage Q into smem (reuse Xs region, partials dead) for a vector write
        float* Qs = Xs;
        #pragma unroll
        for (int r = 0; r < 4; r++) {
            int row = lane + 32 * r;
            if (row < DOUT) {
                #pragma unroll
                for (int k = 0; k < NQ; k++) Qs[row * NQ + k] = q[r][k];
            }
        }
    }
    __syncthreads();

    // ---- coalesced float4 write-out (1000 floats = 250 float4) ----
    {
        const float4* Qs4 = (const float4*)Xs;
        float4* out4 = (float4*)(out + (long long)b * (DOUT * NQ));
        for (int m = tid; m < (DOUT * NQ) / 4; m += NT) out4[m] = Qs4[m];
    }
}

extern "C" void kernel_launch(void* const* d_in, const int* in_sizes, int n_in,
                              void* d_out, int out_size)
{
    const float* X = (const float*)d_in[0];
    const float* W = (const float*)d_in[1];
    if (n_in >= 2 && in_sizes[0] == DOUT * DIN && in_sizes[1] != DOUT * DIN) {
        const float* t = X; X = W; W = t;
    }
    pack_w_kernel<<<(NKP * NP + 255) / 256, 256>>>(W);
    int batches = out_size / (DOUT * NQ);
    frmap_qr_kernel<<<batches, NT>>>(X, (float*)d_out);
}